// round 14
// baseline (speedup 1.0000x reference)
#include <cuda_runtime.h>
#include <cuda_bf16.h>
#include <math.h>

#define NO 64
#define NH 128
#define NB_MAX 600

// Scratch (allocation-free; zero-initialized at module load, re-zeroed by the
// rdf blocks each call so every graph replay starts clean).
__device__ float g_num[32 * 3 * NB_MAX];   // per-(rp,b) rdf numerators
__device__ float g_sumU[32 * 3];           // per-rp sum of frame weights
__device__ unsigned g_cnt;                 // hist-block completion counter
__device__ unsigned g_cnt2;                // rdf-block completion counter

// ---------------------------------------------------------------------------
// Branchless pair visit: min-image distance -> analytic bin -> predicated
// shared red. (bins are linspace; analytic index == searchsorted except for
// d within ~1ulp of an edge -> ±1-bin shifts on ~1e-4 of pairs, ~1e-5 rel.)
// ---------------------------------------------------------------------------
__device__ __forceinline__ void do_pair(
    const float4 A, const float4 B,
    const float L0, const float L1, const float L2,
    const float b0, const float bN, const float inv_dx, const float kc,
    const int nbm1, const unsigned hbase, const int w)
{
    float dx = fabsf(A.x - B.x); dx = fminf(dx, L0 - dx);
    float dy = fabsf(A.y - B.y); dy = fminf(dy, L1 - dy);
    float dz = fabsf(A.z - B.z); dz = fminf(dz, L2 - dz);
    const float s = fmaf(dx, dx, fmaf(dy, dy, dz * dz));

    // d = sqrt(s) via rsqrt.approx + one Newton step (~1 ulp).
    // s == 0 (self pair) -> inf -> NaN -> both range predicates false.
    float y; asm("rsqrt.approx.f32 %0, %1;" : "=f"(y) : "f"(s));
    const float x = s * y;
    const float d = x * fmaf(-0.5f * x, y, 1.5f);

    int k = (int)fmaf(d, inv_dx, kc);
    k = min(max(k, 0), nbm1);

    const int ok = (int)((d >= b0) & (d <= bN));
    const unsigned addr = hbase + ((unsigned)k << 2);
    asm volatile(
        "{\n\t.reg .pred p;\n\t"
        "setp.ne.s32 p, %0, 0;\n\t"
        "@p red.shared.add.u32 [%1], %2;\n\t}"
        :: "r"(ok), "r"(addr), "r"(w) : "memory");
}

// ---------------------------------------------------------------------------
// Fused kernel, grid = R*T hist blocks + R rdf blocks.
// Hist block (bid < R*T): one (replica, frame); all three pair-type
//   histograms; epilogue REDs num[rp,b] += h[b]/u_t, sumU[rp] += u_t; then
//   release-increments g_cnt.
// Rdf block (bid >= R*T): acquire-polls g_cnt == R*T, then computes its
//   replica's 3 rdf rows + MAEs + max, writes out, zeros its scratch slice;
//   the last rdf block resets the counters for the next graph replay.
// ---------------------------------------------------------------------------
__global__ void __launch_bounds__(256, 6) fused_kernel(
    const float* __restrict__ radii,   // (T, R, N, 3)
    const int*   __restrict__ ptypes,  // (N,)
    const float* __restrict__ lat,     // (3,)
    const float* __restrict__ bins,    // (nb+1,)
    const float* __restrict__ gt_oo,
    const float* __restrict__ gt_hh,
    const float* __restrict__ gt_ho,
    float* __restrict__ out,
    int T, int R, int N, int nb)
{
    __shared__ int idxO_s[NO];
    __shared__ int idxH_s[NH];
    __shared__ float4 sO[NO];
    __shared__ float4 sH[NH];
    __shared__ int hOO[NB_MAX];
    __shared__ int hHH[NB_MAX];
    __shared__ int hHO[NB_MAX];
    __shared__ int cO[8], cH[8], oO[8], oH[8];
    __shared__ int totO_s, totH_s;
    __shared__ float usum[8][3];
    __shared__ float ubc[3];

    const int bid = blockIdx.x;
    const int tid = threadIdx.x;
    const int wid = tid >> 5, lane = tid & 31;
    const int histN = R * T;
    const float c43pi = (float)(4.0 / 3.0 * M_PI);

    if (bid >= histN) {
        // ================= rdf block: one replica =================
        const int r = bid - histN;
        float* red = (float*)hOO;              // reuse smem
        float* m3  = (float*)hHH;              // 3 floats

        if (tid == 0) {                        // acquire-poll for all hist done
            unsigned v;
            do {
                asm volatile("ld.acquire.gpu.global.u32 %0, [%1];"
                             : "=r"(v) : "l"(&g_cnt) : "memory");
                if (v == (unsigned)histN) break;
                __nanosleep(200);
            } while (1);
        }
        __syncthreads();

        const float vol = lat[0] * lat[1] * lat[2];
        float* outm = out;
        #pragma unroll
        for (int p = 0; p < 3; p++) {
            const int rp = r * 3 + p;
            const int P = (p == 0) ? NO * NO : (p == 1) ? NH * NH : NH * NO;
            const float SinvT = vol / ((float)T * (float)P) * g_sumU[rp] / (float)T;
            const float* gt = (p == 0) ? gt_oo : (p == 1) ? gt_hh : gt_ho;
            const float* num = g_num + (size_t)rp * NB_MAX;
            float* ro = outm + (size_t)rp * nb;
            float myabs = 0.0f;
            for (int b = tid; b < nb; b += 256) {
                const float lo = bins[b], hi = bins[b + 1];
                const float rdf = SinvT * num[b]
                                  / (c43pi * (hi * hi * hi - lo * lo * lo));
                ro[b] = rdf;
                myabs += fabsf(rdf - gt[b]);
            }
            red[tid] = myabs;
            __syncthreads();
            #pragma unroll
            for (int s = 128; s > 0; s >>= 1) {
                if (tid < s) red[tid] += red[tid + s];
                __syncthreads();
            }
            if (tid == 0) m3[p] = 6.0f * red[0] / (float)nb;   // XLIM * mean
            __syncthreads();
        }

        // zero this replica's scratch slice for the next replay
        float* nz = g_num + (size_t)(r * 3) * NB_MAX;
        for (int i = tid; i < 3 * NB_MAX; i += 256) nz[i] = 0.0f;
        if (tid < 3) g_sumU[r * 3 + tid] = 0.0f;
        __syncthreads();

        if (tid == 0) {
            float m = fmaxf(m3[0], fmaxf(m3[1], m3[2]));
            out[(size_t)R * 3 * nb + r] = m;
            __threadfence();                   // order zeroing before reset
            unsigned old = atomicAdd(&g_cnt2, 1u);
            if (old == (unsigned)(R - 1)) {    // last rdf block resets counters
                g_cnt = 0;
                g_cnt2 = 0;
            }
        }
        return;
    }

    // ================= hist block: one (replica, frame) =================
    const int t = bid % T;
    const int r = bid / T;

    // ---- ballot-compaction of O/H index lists (N <= 256) ----
    const int ty = (tid < N) ? ptypes[tid] : -1;
    const unsigned mO = __ballot_sync(0xffffffffu, ty == 8);
    const unsigned mH = __ballot_sync(0xffffffffu, ty == 1);
    if (lane == 0) { cO[wid] = __popc(mO); cH[wid] = __popc(mH); }
    for (int i = tid; i < nb; i += 256) { hOO[i] = 0; hHH[i] = 0; hHO[i] = 0; }
    __syncthreads();
    if (tid == 0) {
        int aO = 0, aH = 0;
        #pragma unroll
        for (int w = 0; w < 8; w++) {
            oO[w] = aO; aO += cO[w];
            oH[w] = aH; aH += cH[w];
        }
        totO_s = aO; totH_s = aH;
    }
    __syncthreads();
    const unsigned lt = (1u << lane) - 1u;
    if (ty == 8) { int pos = oO[wid] + __popc(mO & lt); if (pos < NO) idxO_s[pos] = tid; }
    if (ty == 1) { int pos = oH[wid] + __popc(mH & lt); if (pos < NH) idxH_s[pos] = tid; }
    for (int j = totO_s + tid; j < NO; j += 256) idxO_s[j] = 0;
    for (int j = totH_s + tid; j < NH; j += 256) idxH_s[j] = 0;
    __syncthreads();

    const float L0 = lat[0], L1 = lat[1], L2 = lat[2];
    const float rL0 = 1.0f / L0, rL1 = 1.0f / L1, rL2 = 1.0f / L2;

    // ---- gather + wrap once: w = frac(x/L)*L (reciprocal-multiply: a floor
    //      flip shifts the coord by ~L, invariant under min-image) ----
    const float* base = radii + ((size_t)t * R + r) * (size_t)N * 3;
    for (int i = tid; i < NO; i += 256) {
        const int g = idxO_s[i];
        float f0 = base[3 * g    ] * rL0;
        float f1 = base[3 * g + 1] * rL1;
        float f2 = base[3 * g + 2] * rL2;
        sO[i] = make_float4((f0 - floorf(f0)) * L0, (f1 - floorf(f1)) * L1,
                            (f2 - floorf(f2)) * L2, 0.0f);
    }
    for (int i = tid; i < NH; i += 256) {
        const int g = idxH_s[i];
        float f0 = base[3 * g    ] * rL0;
        float f1 = base[3 * g + 1] * rL1;
        float f2 = base[3 * g + 2] * rL2;
        sH[i] = make_float4((f0 - floorf(f0)) * L0, (f1 - floorf(f1)) * L1,
                            (f2 - floorf(f2)) * L2, 0.0f);
    }
    __syncthreads();

    const float b0 = bins[0], bN = bins[nb];
    const float inv_dx = (float)nb / (bN - b0);
    const float kc = -b0 * inv_dx;
    const int nbm1 = nb - 1;
    const unsigned hbOO = (unsigned)__cvta_generic_to_shared(hOO);
    const unsigned hbHH = (unsigned)__cvta_generic_to_shared(hHH);
    const unsigned hbHO = (unsigned)__cvta_generic_to_shared(hHO);

    // ---- phase 1: OO (symmetric, n=64; each unordered pair once, w=2;
    //      w=1 at the half-offset -> counts == full double-counted matrix) ----
    {
        const int j  = tid & (NO - 1);
        const int c0 = tid >> 6;                    // 0..3, step 4
        const float4 B = sO[j];
        #pragma unroll
        for (int o = 1 + c0; o <= 32; o += 4) {
            const int i = (j + o) & (NO - 1);
            const int w = (o == 32) ? 1 : 2;
            do_pair(sO[i], B, L0, L1, L2, b0, bN, inv_dx, kc, nbm1, hbOO, w);
        }
    }
    // ---- phase 2: HH (symmetric, n=128) ----
    {
        const int j  = tid & (NH - 1);
        const int c0 = tid >> 7;                    // 0..1, step 2
        const float4 B = sH[j];
        #pragma unroll 8
        for (int o = 1 + c0; o <= 64; o += 2) {
            const int i = (j + o) & (NH - 1);
            const int w = (o == 64) ? 1 : 2;
            do_pair(sH[i], B, L0, L1, L2, b0, bN, inv_dx, kc, nbm1, hbHH, w);
        }
    }
    // ---- phase 3: HO (all 128x64, w=1) ----
    {
        const int j  = tid & (NO - 1);
        const int c0 = tid >> 6;                    // 0..3
        const float4 B = sO[j];
        #pragma unroll 8
        for (int i = c0; i < NH; i += 4) {
            do_pair(sH[i], B, L0, L1, L2, b0, bN, inv_dx, kc, nbm1, hbHO, 1);
        }
    }
    __syncthreads();

    // ---- epilogue: u = sum_b h[b]/shell[b] per pair type ----
    float a0 = 0.0f, a1 = 0.0f, a2 = 0.0f;
    for (int i = tid; i < nb; i += 256) {
        const float lo = bins[i], hi = bins[i + 1];
        const float inv = __fdividef(1.0f, c43pi * (hi * hi * hi - lo * lo * lo));
        a0 = fmaf((float)hOO[i], inv, a0);
        a1 = fmaf((float)hHH[i], inv, a1);
        a2 = fmaf((float)hHO[i], inv, a2);
    }
    #pragma unroll
    for (int o = 16; o > 0; o >>= 1) {
        a0 += __shfl_xor_sync(0xffffffffu, a0, o);
        a1 += __shfl_xor_sync(0xffffffffu, a1, o);
        a2 += __shfl_xor_sync(0xffffffffu, a2, o);
    }
    if (lane == 0) { usum[wid][0] = a0; usum[wid][1] = a1; usum[wid][2] = a2; }
    __syncthreads();
    if (tid == 0) {
        float s0 = 0.0f, s1 = 0.0f, s2 = 0.0f;
        #pragma unroll
        for (int w = 0; w < 8; w++) {
            s0 += usum[w][0]; s1 += usum[w][1]; s2 += usum[w][2];
        }
        ubc[0] = s0; ubc[1] = s1; ubc[2] = s2;
        atomicAdd(&g_sumU[r * 3 + 0], s0);
        atomicAdd(&g_sumU[r * 3 + 1], s1);
        atomicAdd(&g_sumU[r * 3 + 2], s2);
    }
    __syncthreads();

    // ---- accumulate num[rp,b] += h[b]/u directly ----
    const float iu0 = 1.0f / ubc[0];
    const float iu1 = 1.0f / ubc[1];
    const float iu2 = 1.0f / ubc[2];
    float* n0 = g_num + (size_t)(r * 3 + 0) * NB_MAX;
    float* n1 = g_num + (size_t)(r * 3 + 1) * NB_MAX;
    float* n2 = g_num + (size_t)(r * 3 + 2) * NB_MAX;
    for (int i = tid; i < nb; i += 256) {
        const int h0 = hOO[i], h1 = hHH[i], h2 = hHO[i];
        if (h0) atomicAdd(&n0[i], (float)h0 * iu0);
        if (h1) atomicAdd(&n1[i], (float)h1 * iu1);
        if (h2) atomicAdd(&n2[i], (float)h2 * iu2);
    }

    // ---- release: all block's REDs happen-before the counter bump ----
    __syncthreads();
    if (tid == 0) {
        asm volatile("red.release.gpu.global.add.u32 [%0], %1;"
                     :: "l"(&g_cnt), "r"(1u) : "memory");
    }
}

// ---------------------------------------------------------------------------
extern "C" void kernel_launch(void* const* d_in, const int* in_sizes, int n_in,
                              void* d_out, int out_size) {
    const float* radii  = (const float*)d_in[0];   // (T,R,N,3)
    const int*   ptypes = (const int*)d_in[1];     // (N,)
    const float* lat    = (const float*)d_in[2];   // (3,)
    const float* bins   = (const float*)d_in[3];   // (nb+1,)
    const float* gt_oo  = (const float*)d_in[4];
    const float* gt_hh  = (const float*)d_in[5];
    const float* gt_ho  = (const float*)d_in[6];
    float* out = (float*)d_out;

    const int nb = in_sizes[3] - 1;                 // 600
    const int N  = in_sizes[1];                     // 192
    const int R  = out_size / (3 * nb + 1);         // 8
    const int T  = in_sizes[0] / (R * N * 3);       // 100

    fused_kernel<<<R * T + R, 256>>>(radii, ptypes, lat, bins,
                                     gt_oo, gt_hh, gt_ho, out, T, R, N, nb);
}

// round 15
// speedup vs baseline: 1.1251x; 1.1251x over previous
#include <cuda_runtime.h>
#include <cuda_bf16.h>
#include <math.h>

#define NO 64
#define NH 128
#define NB_MAX 600

// Scratch (allocation-free; zero-initialized at module load, re-zeroed by
// rdf_kernel after each use so every graph replay starts clean).
__device__ float g_num[32 * 3 * NB_MAX];   // per-(rp,b) rdf numerators
__device__ float g_sumU[32 * 3];           // per-rp sum of frame weights
__device__ float g_maes[32 * 3];
__device__ unsigned g_cnt;                 // completion counter (reset by last block)

// ---------------------------------------------------------------------------
// Branchless pair visit: min-image distance -> analytic bin -> predicated
// shared red. Single setp.le (d<=bN): NaN (self/duplicate pairs, s==0) is
// false; the d>=1e-6 lower bound only excludes 0<d<1e-6, which cannot occur.
// ---------------------------------------------------------------------------
__device__ __forceinline__ void do_pair(
    const float4 A, const float4 B,
    const float L0, const float L1, const float L2,
    const float bN, const float inv_dx, const float kc,
    const int nbm1, const unsigned hbase, const int w)
{
    float dx = fabsf(A.x - B.x); dx = fminf(dx, L0 - dx);
    float dy = fabsf(A.y - B.y); dy = fminf(dy, L1 - dy);
    float dz = fabsf(A.z - B.z); dz = fminf(dz, L2 - dz);
    const float s = fmaf(dx, dx, fmaf(dy, dy, dz * dz));

    // d = sqrt(s) via rsqrt.approx + one Newton step (~1 ulp); s==0 -> NaN.
    float y; asm("rsqrt.approx.f32 %0, %1;" : "=f"(y) : "f"(s));
    const float x = s * y;
    const float d = x * fmaf(-0.5f * x, y, 1.5f);

    int k = (int)fmaf(d, inv_dx, kc);
    k = min(max(k, 0), nbm1);
    const unsigned addr = hbase + ((unsigned)k << 2);
    asm volatile(
        "{\n\t.reg .pred p;\n\t"
        "setp.le.f32 p, %0, %1;\n\t"
        "@p red.shared.add.u32 [%2], %3;\n\t}"
        :: "f"(d), "f"(bN), "r"(addr), "r"(w) : "memory");
}

// ---------------------------------------------------------------------------
// One block per (replica, frame): all three pair-type histograms with
// shared-A pairing (each LDS'd A point feeds TWO register-resident B points).
// Epilogue REDs num[rp,b] += h[b]/u_t and sumU[rp] += u_t.
// ---------------------------------------------------------------------------
__global__ __launch_bounds__(256) void hist_kernel(
    const float* __restrict__ radii,   // (T, R, N, 3)
    const int*   __restrict__ ptypes,  // (N,)
    const float* __restrict__ lat,     // (3,)
    const float* __restrict__ bins,    // (nb+1,)
    int T, int R, int N, int nb)
{
    __shared__ int idxO_s[NO];
    __shared__ int idxH_s[NH];
    __shared__ float4 sO[NO];
    __shared__ float4 sH[NH];
    __shared__ int hOO[NB_MAX];
    __shared__ int hHH[NB_MAX];
    __shared__ int hHO[NB_MAX];
    __shared__ int cO[8], cH[8], oO[8], oH[8];
    __shared__ int totO_s, totH_s;
    __shared__ float usum[8][3];
    __shared__ float ubc[3];

    const int bid = blockIdx.x;
    const int t = bid % T;
    const int r = bid / T;
    const int tid = threadIdx.x;
    const int wid = tid >> 5, lane = tid & 31;

    // ---- ballot-compaction of O/H index lists (N <= 256) ----
    const int ty = (tid < N) ? ptypes[tid] : -1;
    const unsigned mO = __ballot_sync(0xffffffffu, ty == 8);
    const unsigned mH = __ballot_sync(0xffffffffu, ty == 1);
    if (lane == 0) { cO[wid] = __popc(mO); cH[wid] = __popc(mH); }
    for (int i = tid; i < nb; i += 256) { hOO[i] = 0; hHH[i] = 0; hHO[i] = 0; }
    __syncthreads();
    if (tid == 0) {
        int aO = 0, aH = 0;
        #pragma unroll
        for (int w = 0; w < 8; w++) {
            oO[w] = aO; aO += cO[w];
            oH[w] = aH; aH += cH[w];
        }
        totO_s = aO; totH_s = aH;
    }
    __syncthreads();
    const unsigned lt = (1u << lane) - 1u;
    if (ty == 8) { int pos = oO[wid] + __popc(mO & lt); if (pos < NO) idxO_s[pos] = tid; }
    if (ty == 1) { int pos = oH[wid] + __popc(mH & lt); if (pos < NH) idxH_s[pos] = tid; }
    for (int j = totO_s + tid; j < NO; j += 256) idxO_s[j] = 0;
    for (int j = totH_s + tid; j < NH; j += 256) idxH_s[j] = 0;
    __syncthreads();

    const float L0 = lat[0], L1 = lat[1], L2 = lat[2];
    const float rL0 = 1.0f / L0, rL1 = 1.0f / L1, rL2 = 1.0f / L2;

    // ---- gather + wrap once: w = frac(x/L)*L (reciprocal-multiply: a floor
    //      flip shifts the coord by ~L, invariant under min-image) ----
    const float* base = radii + ((size_t)t * R + r) * (size_t)N * 3;
    for (int i = tid; i < NO; i += 256) {
        const int g = idxO_s[i];
        float f0 = base[3 * g    ] * rL0;
        float f1 = base[3 * g + 1] * rL1;
        float f2 = base[3 * g + 2] * rL2;
        sO[i] = make_float4((f0 - floorf(f0)) * L0, (f1 - floorf(f1)) * L1,
                            (f2 - floorf(f2)) * L2, 0.0f);
    }
    for (int i = tid; i < NH; i += 256) {
        const int g = idxH_s[i];
        float f0 = base[3 * g    ] * rL0;
        float f1 = base[3 * g + 1] * rL1;
        float f2 = base[3 * g + 2] * rL2;
        sH[i] = make_float4((f0 - floorf(f0)) * L0, (f1 - floorf(f1)) * L1,
                            (f2 - floorf(f2)) * L2, 0.0f);
    }
    __syncthreads();

    const float b0 = bins[0], bN = bins[nb];
    const float inv_dx = (float)nb / (bN - b0);
    const float kc = -b0 * inv_dx;
    const int nbm1 = nb - 1;
    const unsigned hbOO = (unsigned)__cvta_generic_to_shared(hOO);
    const unsigned hbHH = (unsigned)__cvta_generic_to_shared(hHH);
    const unsigned hbHO = (unsigned)__cvta_generic_to_shared(hHO);

    // ---- phase 1: OO (symmetric, n=64). Shared-A: for o in 17..32,
    //      A=sO[j+o] serves pair(j+o, j) [offset o, w=(o==32)?1:2] and
    //      pair(j+o, j+16) [offset o-16 in 1..16, w=2]. Exact cover of
    //      o=1..32; counts == full double-counted matrix. ----
    {
        const int j  = tid & (NO - 1);
        const int c0 = tid >> 6;                    // 0..3, step 4
        const float4 B1 = sO[j];
        const float4 B2 = sO[(j + 16) & (NO - 1)];
        #pragma unroll
        for (int o = 17 + c0; o <= 32; o += 4) {
            const float4 A = sO[(j + o) & (NO - 1)];
            const int w1 = (o == 32) ? 1 : 2;
            do_pair(A, B1, L0, L1, L2, bN, inv_dx, kc, nbm1, hbOO, w1);
            do_pair(A, B2, L0, L1, L2, bN, inv_dx, kc, nbm1, hbOO, 2);
        }
    }
    // ---- phase 2: HH (symmetric, n=128). Shared-A: for o in 33..64,
    //      A=sH[j+o] serves offsets o (w=(o==64)?1:2) and o-32 in 1..32
    //      (w=2; o-32 never reaches the half-offset 64). ----
    {
        const int j  = tid & (NH - 1);
        const int c0 = tid >> 7;                    // 0..1, step 2
        const float4 B1 = sH[j];
        const float4 B2 = sH[(j + 32) & (NH - 1)];
        #pragma unroll 4
        for (int o = 33 + c0; o <= 64; o += 2) {
            const float4 A = sH[(j + o) & (NH - 1)];
            const int w1 = (o == 64) ? 1 : 2;
            do_pair(A, B1, L0, L1, L2, bN, inv_dx, kc, nbm1, hbHH, w1);
            do_pair(A, B2, L0, L1, L2, bN, inv_dx, kc, nbm1, hbHH, 2);
        }
    }
    // ---- phase 3: HO (all 128x64, w=1). Shared-A: A=sH[i] pairs with
    //      both B1=sO[j] and B2=sO[j+32], j in 0..31. ----
    {
        const int j  = tid & 31;
        const int c0 = tid >> 5;                    // 0..7, step 8
        const float4 B1 = sO[j];
        const float4 B2 = sO[j + 32];
        #pragma unroll 4
        for (int i = c0; i < NH; i += 8) {
            const float4 A = sH[i];
            do_pair(A, B1, L0, L1, L2, bN, inv_dx, kc, nbm1, hbHO, 1);
            do_pair(A, B2, L0, L1, L2, bN, inv_dx, kc, nbm1, hbHO, 1);
        }
    }
    __syncthreads();

    // ---- epilogue: u = sum_b h[b]/shell[b] per pair type ----
    const float c43pi = (float)(4.0 / 3.0 * M_PI);
    float a0 = 0.0f, a1 = 0.0f, a2 = 0.0f;
    for (int i = tid; i < nb; i += 256) {
        const float lo = bins[i], hi = bins[i + 1];
        const float inv = __fdividef(1.0f, c43pi * (hi * hi * hi - lo * lo * lo));
        a0 = fmaf((float)hOO[i], inv, a0);
        a1 = fmaf((float)hHH[i], inv, a1);
        a2 = fmaf((float)hHO[i], inv, a2);
    }
    #pragma unroll
    for (int o = 16; o > 0; o >>= 1) {
        a0 += __shfl_xor_sync(0xffffffffu, a0, o);
        a1 += __shfl_xor_sync(0xffffffffu, a1, o);
        a2 += __shfl_xor_sync(0xffffffffu, a2, o);
    }
    if (lane == 0) { usum[wid][0] = a0; usum[wid][1] = a1; usum[wid][2] = a2; }
    __syncthreads();
    if (tid == 0) {
        float s0 = 0.0f, s1 = 0.0f, s2 = 0.0f;
        #pragma unroll
        for (int w = 0; w < 8; w++) {
            s0 += usum[w][0]; s1 += usum[w][1]; s2 += usum[w][2];
        }
        ubc[0] = s0; ubc[1] = s1; ubc[2] = s2;
        atomicAdd(&g_sumU[r * 3 + 0], s0);
        atomicAdd(&g_sumU[r * 3 + 1], s1);
        atomicAdd(&g_sumU[r * 3 + 2], s2);
    }
    __syncthreads();

    // ---- accumulate num[rp,b] += h[b]/u directly ----
    const float iu0 = 1.0f / ubc[0];
    const float iu1 = 1.0f / ubc[1];
    const float iu2 = 1.0f / ubc[2];
    float* n0 = g_num + (size_t)(r * 3 + 0) * NB_MAX;
    float* n1 = g_num + (size_t)(r * 3 + 1) * NB_MAX;
    float* n2 = g_num + (size_t)(r * 3 + 2) * NB_MAX;
    for (int i = tid; i < nb; i += 256) {
        const int h0 = hOO[i], h1 = hHH[i], h2 = hHO[i];
        if (h0) atomicAdd(&n0[i], (float)h0 * iu0);
        if (h1) atomicAdd(&n1[i], (float)h1 * iu1);
        if (h2) atomicAdd(&n2[i], (float)h2 * iu2);
    }
}

// ---------------------------------------------------------------------------
// rdf + MAE from accumulated numerators: blockIdx.x = rp (24 blocks).
// rdf[b] = (sumU * vol/(T*P)/T) * num[b] / shell[b]. Re-zeros its scratch
// for the next graph replay; last block finalizes the per-replica MAE max.
// ---------------------------------------------------------------------------
__global__ __launch_bounds__(256) void rdf_kernel(
    const float* __restrict__ bins,
    const float* __restrict__ lat,
    const float* __restrict__ gt_oo,
    const float* __restrict__ gt_hh,
    const float* __restrict__ gt_ho,
    float* __restrict__ out,
    int T, int nb, int R)
{
    __shared__ float red[256];
    __shared__ int sdone;

    const int rp = blockIdx.x;
    const int p = rp % 3;
    const int r = rp / 3;
    const int tid = threadIdx.x;

    const float vol = lat[0] * lat[1] * lat[2];
    const int P = (p == 0) ? NO * NO : (p == 1) ? NH * NH : NH * NO;
    const float sumU = g_sumU[rp];
    const float SinvT = vol / ((float)T * (float)P) * sumU / (float)T;
    const float* gt = (p == 0) ? gt_oo : (p == 1) ? gt_hh : gt_ho;
    const float* num = g_num + (size_t)rp * NB_MAX;
    const float c43pi = (float)(4.0 / 3.0 * M_PI);

    float* ro = out + ((size_t)r * 3 + p) * nb;
    float myabs = 0.0f;
    for (int b = tid; b < nb; b += 256) {
        const float lo = bins[b], hi = bins[b + 1];
        const float rdf = SinvT * num[b] / (c43pi * (hi * hi * hi - lo * lo * lo));
        ro[b] = rdf;
        myabs += fabsf(rdf - gt[b]);
    }
    red[tid] = myabs;
    __syncthreads();

    // re-zero scratch for the next replay (all reads of num/sumU are done)
    for (int b = tid; b < nb; b += 256) ((float*)num)[b] = 0.0f;
    if (tid == 0) g_sumU[rp] = 0.0f;

    #pragma unroll
    for (int s = 128; s > 0; s >>= 1) {
        if (tid < s) red[tid] += red[tid + s];
        __syncthreads();
    }
    if (tid == 0) {
        g_maes[rp] = 6.0f * red[0] / (float)nb;   // XLIM * mean
        __threadfence();
        unsigned old = atomicAdd(&g_cnt, 1u);
        sdone = (int)(old == (unsigned)(3 * R - 1));
    }
    __syncthreads();
    if (sdone) {
        __threadfence();
        if (tid == 0) g_cnt = 0;                  // reset for next graph replay
        if (tid < R) {
            volatile float* gm = g_maes;
            float m = gm[tid * 3];
            m = fmaxf(m, gm[tid * 3 + 1]);
            m = fmaxf(m, gm[tid * 3 + 2]);
            out[(size_t)R * 3 * nb + tid] = m;
        }
    }
}

// ---------------------------------------------------------------------------
extern "C" void kernel_launch(void* const* d_in, const int* in_sizes, int n_in,
                              void* d_out, int out_size) {
    const float* radii  = (const float*)d_in[0];   // (T,R,N,3)
    const int*   ptypes = (const int*)d_in[1];     // (N,)
    const float* lat    = (const float*)d_in[2];   // (3,)
    const float* bins   = (const float*)d_in[3];   // (nb+1,)
    const float* gt_oo  = (const float*)d_in[4];
    const float* gt_hh  = (const float*)d_in[5];
    const float* gt_ho  = (const float*)d_in[6];
    float* out = (float*)d_out;

    const int nb = in_sizes[3] - 1;                 // 600
    const int N  = in_sizes[1];                     // 192
    const int R  = out_size / (3 * nb + 1);         // 8
    const int T  = in_sizes[0] / (R * N * 3);       // 100

    hist_kernel<<<R * T, 256>>>(radii, ptypes, lat, bins, T, R, N, nb);
    rdf_kernel<<<R * 3, 256>>>(bins, lat, gt_oo, gt_hh, gt_ho, out, T, nb, R);
}

// round 16
// speedup vs baseline: 1.1972x; 1.0640x over previous
#include <cuda_runtime.h>
#include <cuda_bf16.h>
#include <math.h>

#define NO 64
#define NH 128
#define NB_MAX 600

// Scratch (allocation-free; zero-initialized at module load, re-zeroed by
// rdf_kernel after each use so every graph replay starts clean).
__device__ float g_num[32 * 3 * NB_MAX];   // per-(rp,b) rdf numerators
__device__ float g_sumU[32 * 3];           // per-rp sum of frame weights
__device__ float g_maes[32 * 3];
__device__ unsigned g_cnt;                 // completion counter (reset by last block)

// ---------------------------------------------------------------------------
// Branchless pair visit: min-image distance -> analytic bin -> predicated
// shared red. Single setp.le (d<=bN): NaN (self/duplicate pairs, s==0) is
// false. k needs no lower clamp: d>=0 -> fma >= kc ~ -1e-4 -> trunc -> 0;
// NaN -> 0. When d>bN (RED predicated off) k may exceed range harmlessly.
// ---------------------------------------------------------------------------
__device__ __forceinline__ void do_pair(
    const float4 A, const float4 B,
    const float L0, const float L1, const float L2,
    const float bN, const float inv_dx, const float kc,
    const int nbm1, const unsigned hbase, const int w)
{
    float dx = fabsf(A.x - B.x); dx = fminf(dx, L0 - dx);
    float dy = fabsf(A.y - B.y); dy = fminf(dy, L1 - dy);
    float dz = fabsf(A.z - B.z); dz = fminf(dz, L2 - dz);
    const float s = fmaf(dx, dx, fmaf(dy, dy, dz * dz));

    // d = sqrt(s) via rsqrt.approx + one Newton step (~1 ulp); s==0 -> NaN.
    float y; asm("rsqrt.approx.f32 %0, %1;" : "=f"(y) : "f"(s));
    const float x = s * y;
    const float d = x * fmaf(-0.5f * x, y, 1.5f);

    int k = (int)fmaf(d, inv_dx, kc);
    k = min(k, nbm1);
    const unsigned addr = hbase + ((unsigned)k << 2);
    asm volatile(
        "{\n\t.reg .pred p;\n\t"
        "setp.le.f32 p, %0, %1;\n\t"
        "@p red.shared.add.u32 [%2], %3;\n\t}"
        :: "f"(d), "f"(bN), "r"(addr), "r"(w) : "memory");
}

// ---------------------------------------------------------------------------
// One block per (replica, frame): all three pair-type histograms with 4-way
// shared-A pairing (each LDS'd A point feeds FOUR register-resident B points).
// Epilogue REDs num[rp,b] += h[b]/u_t and sumU[rp] += u_t.
// ---------------------------------------------------------------------------
__global__ __launch_bounds__(256) void hist_kernel(
    const float* __restrict__ radii,   // (T, R, N, 3)
    const int*   __restrict__ ptypes,  // (N,)
    const float* __restrict__ lat,     // (3,)
    const float* __restrict__ bins,    // (nb+1,)
    int T, int R, int N, int nb)
{
    __shared__ int idxO_s[NO];
    __shared__ int idxH_s[NH];
    __shared__ float4 sO[NO];
    __shared__ float4 sH[NH];
    __shared__ int hOO[NB_MAX];
    __shared__ int hHH[NB_MAX];
    __shared__ int hHO[NB_MAX];
    __shared__ int cO[8], cH[8], oO[8], oH[8];
    __shared__ int totO_s, totH_s;
    __shared__ float usum[8][3];
    __shared__ float ubc[3];

    const int bid = blockIdx.x;
    const int t = bid % T;
    const int r = bid / T;
    const int tid = threadIdx.x;
    const int wid = tid >> 5, lane = tid & 31;

    // ---- ballot-compaction of O/H index lists (N <= 256) ----
    const int ty = (tid < N) ? ptypes[tid] : -1;
    const unsigned mO = __ballot_sync(0xffffffffu, ty == 8);
    const unsigned mH = __ballot_sync(0xffffffffu, ty == 1);
    if (lane == 0) { cO[wid] = __popc(mO); cH[wid] = __popc(mH); }
    for (int i = tid; i < nb; i += 256) { hOO[i] = 0; hHH[i] = 0; hHO[i] = 0; }
    __syncthreads();
    if (tid == 0) {
        int aO = 0, aH = 0;
        #pragma unroll
        for (int w = 0; w < 8; w++) {
            oO[w] = aO; aO += cO[w];
            oH[w] = aH; aH += cH[w];
        }
        totO_s = aO; totH_s = aH;
    }
    __syncthreads();
    const unsigned lt = (1u << lane) - 1u;
    if (ty == 8) { int pos = oO[wid] + __popc(mO & lt); if (pos < NO) idxO_s[pos] = tid; }
    if (ty == 1) { int pos = oH[wid] + __popc(mH & lt); if (pos < NH) idxH_s[pos] = tid; }
    for (int j = totO_s + tid; j < NO; j += 256) idxO_s[j] = 0;
    for (int j = totH_s + tid; j < NH; j += 256) idxH_s[j] = 0;
    __syncthreads();

    const float L0 = lat[0], L1 = lat[1], L2 = lat[2];
    const float rL0 = 1.0f / L0, rL1 = 1.0f / L1, rL2 = 1.0f / L2;

    // ---- gather + wrap once: w = frac(x/L)*L (reciprocal-multiply: a floor
    //      flip shifts the coord by ~L, invariant under min-image) ----
    const float* base = radii + ((size_t)t * R + r) * (size_t)N * 3;
    for (int i = tid; i < NO; i += 256) {
        const int g = idxO_s[i];
        float f0 = base[3 * g    ] * rL0;
        float f1 = base[3 * g + 1] * rL1;
        float f2 = base[3 * g + 2] * rL2;
        sO[i] = make_float4((f0 - floorf(f0)) * L0, (f1 - floorf(f1)) * L1,
                            (f2 - floorf(f2)) * L2, 0.0f);
    }
    for (int i = tid; i < NH; i += 256) {
        const int g = idxH_s[i];
        float f0 = base[3 * g    ] * rL0;
        float f1 = base[3 * g + 1] * rL1;
        float f2 = base[3 * g + 2] * rL2;
        sH[i] = make_float4((f0 - floorf(f0)) * L0, (f1 - floorf(f1)) * L1,
                            (f2 - floorf(f2)) * L2, 0.0f);
    }
    __syncthreads();

    const float b0 = bins[0], bN = bins[nb];
    const float inv_dx = (float)nb / (bN - b0);
    const float kc = -b0 * inv_dx;
    const int nbm1 = nb - 1;
    const unsigned hbOO = (unsigned)__cvta_generic_to_shared(hOO);
    const unsigned hbHH = (unsigned)__cvta_generic_to_shared(hHH);
    const unsigned hbHO = (unsigned)__cvta_generic_to_shared(hHO);

    // ---- phase 1: OO (symmetric, n=64). 4-way shared-A: for o in 25..32,
    //      A=sO[j+o] serves offsets {o, o-8, o-16, o-24} which tile 1..32.
    //      w=2 everywhere except (B0, o=32) -> w=1. Counts == full matrix. ----
    {
        const int j  = tid & (NO - 1);
        const int c0 = tid >> 6;                    // 0..3, step 4
        const float4 B0 = sO[j];
        const float4 B1 = sO[(j +  8) & (NO - 1)];
        const float4 B2 = sO[(j + 16) & (NO - 1)];
        const float4 B3 = sO[(j + 24) & (NO - 1)];
        #pragma unroll
        for (int o = 25 + c0; o <= 32; o += 4) {
            const float4 A = sO[(j + o) & (NO - 1)];
            const int w0 = (o == 32) ? 1 : 2;
            do_pair(A, B0, L0, L1, L2, bN, inv_dx, kc, nbm1, hbOO, w0);
            do_pair(A, B1, L0, L1, L2, bN, inv_dx, kc, nbm1, hbOO, 2);
            do_pair(A, B2, L0, L1, L2, bN, inv_dx, kc, nbm1, hbOO, 2);
            do_pair(A, B3, L0, L1, L2, bN, inv_dx, kc, nbm1, hbOO, 2);
        }
    }
    // ---- phase 2: HH (symmetric, n=128). 4-way shared-A: for o in 49..64,
    //      A=sH[j+o] serves offsets {o, o-16, o-32, o-48} which tile 1..64.
    //      w=2 everywhere except (B0, o=64) -> w=1. ----
    {
        const int j  = tid & (NH - 1);
        const int c0 = tid >> 7;                    // 0..1, step 2
        const float4 B0 = sH[j];
        const float4 B1 = sH[(j + 16) & (NH - 1)];
        const float4 B2 = sH[(j + 32) & (NH - 1)];
        const float4 B3 = sH[(j + 48) & (NH - 1)];
        #pragma unroll 4
        for (int o = 49 + c0; o <= 64; o += 2) {
            const float4 A = sH[(j + o) & (NH - 1)];
            const int w0 = (o == 64) ? 1 : 2;
            do_pair(A, B0, L0, L1, L2, bN, inv_dx, kc, nbm1, hbHH, w0);
            do_pair(A, B1, L0, L1, L2, bN, inv_dx, kc, nbm1, hbHH, 2);
            do_pair(A, B2, L0, L1, L2, bN, inv_dx, kc, nbm1, hbHH, 2);
            do_pair(A, B3, L0, L1, L2, bN, inv_dx, kc, nbm1, hbHH, 2);
        }
    }
    // ---- phase 3: HO (all 128x64, w=1). 4-way shared-A: A=sH[i] pairs with
    //      B = sO[j], sO[j+16], sO[j+32], sO[j+48], j in 0..15. ----
    {
        const int j  = tid & 15;
        const int c0 = tid >> 4;                    // 0..15, step 16
        const float4 B0 = sO[j];
        const float4 B1 = sO[j + 16];
        const float4 B2 = sO[j + 32];
        const float4 B3 = sO[j + 48];
        #pragma unroll 4
        for (int i = c0; i < NH; i += 16) {
            const float4 A = sH[i];
            do_pair(A, B0, L0, L1, L2, bN, inv_dx, kc, nbm1, hbHO, 1);
            do_pair(A, B1, L0, L1, L2, bN, inv_dx, kc, nbm1, hbHO, 1);
            do_pair(A, B2, L0, L1, L2, bN, inv_dx, kc, nbm1, hbHO, 1);
            do_pair(A, B3, L0, L1, L2, bN, inv_dx, kc, nbm1, hbHO, 1);
        }
    }
    __syncthreads();

    // ---- epilogue: u = sum_b h[b]/shell[b] per pair type ----
    const float c43pi = (float)(4.0 / 3.0 * M_PI);
    float a0 = 0.0f, a1 = 0.0f, a2 = 0.0f;
    for (int i = tid; i < nb; i += 256) {
        const float lo = bins[i], hi = bins[i + 1];
        const float inv = __fdividef(1.0f, c43pi * (hi * hi * hi - lo * lo * lo));
        a0 = fmaf((float)hOO[i], inv, a0);
        a1 = fmaf((float)hHH[i], inv, a1);
        a2 = fmaf((float)hHO[i], inv, a2);
    }
    #pragma unroll
    for (int o = 16; o > 0; o >>= 1) {
        a0 += __shfl_xor_sync(0xffffffffu, a0, o);
        a1 += __shfl_xor_sync(0xffffffffu, a1, o);
        a2 += __shfl_xor_sync(0xffffffffu, a2, o);
    }
    if (lane == 0) { usum[wid][0] = a0; usum[wid][1] = a1; usum[wid][2] = a2; }
    __syncthreads();
    if (tid == 0) {
        float s0 = 0.0f, s1 = 0.0f, s2 = 0.0f;
        #pragma unroll
        for (int w = 0; w < 8; w++) {
            s0 += usum[w][0]; s1 += usum[w][1]; s2 += usum[w][2];
        }
        ubc[0] = s0; ubc[1] = s1; ubc[2] = s2;
        atomicAdd(&g_sumU[r * 3 + 0], s0);
        atomicAdd(&g_sumU[r * 3 + 1], s1);
        atomicAdd(&g_sumU[r * 3 + 2], s2);
    }
    __syncthreads();

    // ---- accumulate num[rp,b] += h[b]/u directly ----
    const float iu0 = 1.0f / ubc[0];
    const float iu1 = 1.0f / ubc[1];
    const float iu2 = 1.0f / ubc[2];
    float* n0 = g_num + (size_t)(r * 3 + 0) * NB_MAX;
    float* n1 = g_num + (size_t)(r * 3 + 1) * NB_MAX;
    float* n2 = g_num + (size_t)(r * 3 + 2) * NB_MAX;
    for (int i = tid; i < nb; i += 256) {
        const int h0 = hOO[i], h1 = hHH[i], h2 = hHO[i];
        if (h0) atomicAdd(&n0[i], (float)h0 * iu0);
        if (h1) atomicAdd(&n1[i], (float)h1 * iu1);
        if (h2) atomicAdd(&n2[i], (float)h2 * iu2);
    }
}

// ---------------------------------------------------------------------------
// rdf + MAE from accumulated numerators: blockIdx.x = rp (24 blocks).
// rdf[b] = (sumU * vol/(T*P)/T) * num[b] / shell[b]. Re-zeros its scratch
// for the next graph replay; last block finalizes the per-replica MAE max.
// ---------------------------------------------------------------------------
__global__ __launch_bounds__(256) void rdf_kernel(
    const float* __restrict__ bins,
    const float* __restrict__ lat,
    const float* __restrict__ gt_oo,
    const float* __restrict__ gt_hh,
    const float* __restrict__ gt_ho,
    float* __restrict__ out,
    int T, int nb, int R)
{
    __shared__ float red[256];
    __shared__ int sdone;

    const int rp = blockIdx.x;
    const int p = rp % 3;
    const int r = rp / 3;
    const int tid = threadIdx.x;

    const float vol = lat[0] * lat[1] * lat[2];
    const int P = (p == 0) ? NO * NO : (p == 1) ? NH * NH : NH * NO;
    const float sumU = g_sumU[rp];
    const float SinvT = vol / ((float)T * (float)P) * sumU / (float)T;
    const float* gt = (p == 0) ? gt_oo : (p == 1) ? gt_hh : gt_ho;
    const float* num = g_num + (size_t)rp * NB_MAX;
    const float c43pi = (float)(4.0 / 3.0 * M_PI);

    float* ro = out + ((size_t)r * 3 + p) * nb;
    float myabs = 0.0f;
    for (int b = tid; b < nb; b += 256) {
        const float lo = bins[b], hi = bins[b + 1];
        const float rdf = SinvT * num[b] / (c43pi * (hi * hi * hi - lo * lo * lo));
        ro[b] = rdf;
        myabs += fabsf(rdf - gt[b]);
    }
    red[tid] = myabs;
    __syncthreads();

    // re-zero scratch for the next replay (all reads of num/sumU are done)
    for (int b = tid; b < nb; b += 256) ((float*)num)[b] = 0.0f;
    if (tid == 0) g_sumU[rp] = 0.0f;

    #pragma unroll
    for (int s = 128; s > 0; s >>= 1) {
        if (tid < s) red[tid] += red[tid + s];
        __syncthreads();
    }
    if (tid == 0) {
        g_maes[rp] = 6.0f * red[0] / (float)nb;   // XLIM * mean
        __threadfence();
        unsigned old = atomicAdd(&g_cnt, 1u);
        sdone = (int)(old == (unsigned)(3 * R - 1));
    }
    __syncthreads();
    if (sdone) {
        __threadfence();
        if (tid == 0) g_cnt = 0;                  // reset for next graph replay
        if (tid < R) {
            volatile float* gm = g_maes;
            float m = gm[tid * 3];
            m = fmaxf(m, gm[tid * 3 + 1]);
            m = fmaxf(m, gm[tid * 3 + 2]);
            out[(size_t)R * 3 * nb + tid] = m;
        }
    }
}

// ---------------------------------------------------------------------------
extern "C" void kernel_launch(void* const* d_in, const int* in_sizes, int n_in,
                              void* d_out, int out_size) {
    const float* radii  = (const float*)d_in[0];   // (T,R,N,3)
    const int*   ptypes = (const int*)d_in[1];     // (N,)
    const float* lat    = (const float*)d_in[2];   // (3,)
    const float* bins   = (const float*)d_in[3];   // (nb+1,)
    const float* gt_oo  = (const float*)d_in[4];
    const float* gt_hh  = (const float*)d_in[5];
    const float* gt_ho  = (const float*)d_in[6];
    float* out = (float*)d_out;

    const int nb = in_sizes[3] - 1;                 // 600
    const int N  = in_sizes[1];                     // 192
    const int R  = out_size / (3 * nb + 1);         // 8
    const int T  = in_sizes[0] / (R * N * 3);       // 100

    hist_kernel<<<R * T, 256>>>(radii, ptypes, lat, bins, T, R, N, nb);
    rdf_kernel<<<R * 3, 256>>>(bins, lat, gt_oo, gt_hh, gt_ho, out, T, nb, R);
}

// round 17
// speedup vs baseline: 1.2818x; 1.0707x over previous
#include <cuda_runtime.h>
#include <cuda_bf16.h>
#include <math.h>

#define NO 64
#define NH 128
#define NB_MAX 600

// Scratch (allocation-free; zero-initialized at module load, re-zeroed by
// rdf_kernel after each use so every graph replay starts clean).
__device__ float g_num[32 * 3 * NB_MAX];   // per-(rp,b) rdf numerators
__device__ float g_sumU[32 * 3];           // per-rp sum of frame weights
__device__ float g_maes[32 * 3];
__device__ unsigned g_cnt;                 // completion counter (reset by last block)

// ---------------------------------------------------------------------------
// Branchless pair visit: min-image distance -> analytic bin -> predicated
// shared red. d = s * rsqrt.approx(s): s==0 (self pairs) -> 0*inf = NaN ->
// setp.le false. No clamps on k: d>=0 -> k>=0; k==nb only when d==bN exactly
// (measure-zero) and lands in the histogram's junk slot (size NB_MAX+1);
// k>nb occurs only with the RED predicated off (address never accessed).
// ---------------------------------------------------------------------------
__device__ __forceinline__ void do_pair(
    const float4 A, const float4 B,
    const float L0, const float L1, const float L2,
    const float bN, const float inv_dx, const float kc,
    const unsigned hbase, const int w)
{
    float dx = fabsf(A.x - B.x); dx = fminf(dx, L0 - dx);
    float dy = fabsf(A.y - B.y); dy = fminf(dy, L1 - dy);
    float dz = fabsf(A.z - B.z); dz = fminf(dz, L2 - dz);
    const float s = fmaf(dx, dx, fmaf(dy, dy, dz * dz));

    float y; asm("rsqrt.approx.f32 %0, %1;" : "=f"(y) : "f"(s));
    const float d = s * y;                     // ~2e-7 rel err; NaN at s==0

    const int k = (int)fmaf(d, inv_dx, kc);
    const unsigned addr = hbase + ((unsigned)k << 2);
    asm volatile(
        "{\n\t.reg .pred p;\n\t"
        "setp.le.f32 p, %0, %1;\n\t"
        "@p red.shared.add.u32 [%2], %3;\n\t}"
        :: "f"(d), "f"(bN), "r"(addr), "r"(w) : "memory");
}

// ---------------------------------------------------------------------------
// One block per (replica, frame): all three pair-type histograms with 4-way
// shared-A pairing (each LDS'd A point feeds FOUR register-resident B points).
// Epilogue REDs num[rp,b] += h[b]/u_t and sumU[rp] += u_t.
// ---------------------------------------------------------------------------
__global__ __launch_bounds__(256) void hist_kernel(
    const float* __restrict__ radii,   // (T, R, N, 3)
    const int*   __restrict__ ptypes,  // (N,)
    const float* __restrict__ lat,     // (3,)
    const float* __restrict__ bins,    // (nb+1,)
    int T, int R, int N, int nb)
{
    __shared__ int idxO_s[NO];
    __shared__ int idxH_s[NH];
    __shared__ float4 sO[NO];
    __shared__ float4 sH[NH];
    __shared__ int hOO[NB_MAX + 1];    // +1 junk slot (d==bN measure-zero case)
    __shared__ int hHH[NB_MAX + 1];
    __shared__ int hHO[NB_MAX + 1];
    __shared__ int cO[8], cH[8], oO[8], oH[8];
    __shared__ int totO_s, totH_s;
    __shared__ float usum[8][3];
    __shared__ float ubc[3];

    const int bid = blockIdx.x;
    const int t = bid % T;
    const int r = bid / T;
    const int tid = threadIdx.x;
    const int wid = tid >> 5, lane = tid & 31;

    // ---- ballot-compaction of O/H index lists (N <= 256) ----
    const int ty = (tid < N) ? ptypes[tid] : -1;
    const unsigned mO = __ballot_sync(0xffffffffu, ty == 8);
    const unsigned mH = __ballot_sync(0xffffffffu, ty == 1);
    if (lane == 0) { cO[wid] = __popc(mO); cH[wid] = __popc(mH); }
    for (int i = tid; i < nb; i += 256) { hOO[i] = 0; hHH[i] = 0; hHO[i] = 0; }
    __syncthreads();
    if (tid == 0) {
        int aO = 0, aH = 0;
        #pragma unroll
        for (int w = 0; w < 8; w++) {
            oO[w] = aO; aO += cO[w];
            oH[w] = aH; aH += cH[w];
        }
        totO_s = aO; totH_s = aH;
    }
    __syncthreads();
    const unsigned lt = (1u << lane) - 1u;
    if (ty == 8) { int pos = oO[wid] + __popc(mO & lt); if (pos < NO) idxO_s[pos] = tid; }
    if (ty == 1) { int pos = oH[wid] + __popc(mH & lt); if (pos < NH) idxH_s[pos] = tid; }
    for (int j = totO_s + tid; j < NO; j += 256) idxO_s[j] = 0;
    for (int j = totH_s + tid; j < NH; j += 256) idxH_s[j] = 0;
    __syncthreads();

    const float L0 = lat[0], L1 = lat[1], L2 = lat[2];
    const float rL0 = 1.0f / L0, rL1 = 1.0f / L1, rL2 = 1.0f / L2;

    // ---- gather + wrap once: w = frac(x/L)*L (reciprocal-multiply: a floor
    //      flip shifts the coord by ~L, invariant under min-image) ----
    const float* base = radii + ((size_t)t * R + r) * (size_t)N * 3;
    for (int i = tid; i < NO; i += 256) {
        const int g = idxO_s[i];
        float f0 = base[3 * g    ] * rL0;
        float f1 = base[3 * g + 1] * rL1;
        float f2 = base[3 * g + 2] * rL2;
        sO[i] = make_float4((f0 - floorf(f0)) * L0, (f1 - floorf(f1)) * L1,
                            (f2 - floorf(f2)) * L2, 0.0f);
    }
    for (int i = tid; i < NH; i += 256) {
        const int g = idxH_s[i];
        float f0 = base[3 * g    ] * rL0;
        float f1 = base[3 * g + 1] * rL1;
        float f2 = base[3 * g + 2] * rL2;
        sH[i] = make_float4((f0 - floorf(f0)) * L0, (f1 - floorf(f1)) * L1,
                            (f2 - floorf(f2)) * L2, 0.0f);
    }
    __syncthreads();

    const float b0 = bins[0], bN = bins[nb];
    const float inv_dx = (float)nb / (bN - b0);
    const float kc = -b0 * inv_dx;
    const unsigned hbOO = (unsigned)__cvta_generic_to_shared(hOO);
    const unsigned hbHH = (unsigned)__cvta_generic_to_shared(hHH);
    const unsigned hbHO = (unsigned)__cvta_generic_to_shared(hHO);

    // ---- phase 1: OO (symmetric, n=64). 4-way shared-A: for o in 25..32,
    //      A=sO[j+o] serves offsets {o, o-8, o-16, o-24} which tile 1..32.
    //      w=2 everywhere except (B0, o=32) -> w=1. Counts == full matrix. ----
    {
        const int j  = tid & (NO - 1);
        const int c0 = tid >> 6;                    // 0..3, step 4
        const float4 B0 = sO[j];
        const float4 B1 = sO[(j +  8) & (NO - 1)];
        const float4 B2 = sO[(j + 16) & (NO - 1)];
        const float4 B3 = sO[(j + 24) & (NO - 1)];
        #pragma unroll
        for (int o = 25 + c0; o <= 32; o += 4) {
            const float4 A = sO[(j + o) & (NO - 1)];
            const int w0 = (o == 32) ? 1 : 2;
            do_pair(A, B0, L0, L1, L2, bN, inv_dx, kc, hbOO, w0);
            do_pair(A, B1, L0, L1, L2, bN, inv_dx, kc, hbOO, 2);
            do_pair(A, B2, L0, L1, L2, bN, inv_dx, kc, hbOO, 2);
            do_pair(A, B3, L0, L1, L2, bN, inv_dx, kc, hbOO, 2);
        }
    }
    // ---- phase 2: HH (symmetric, n=128). 4-way shared-A: for o in 49..64,
    //      A=sH[j+o] serves offsets {o, o-16, o-32, o-48} which tile 1..64.
    //      w=2 everywhere except (B0, o=64) -> w=1. ----
    {
        const int j  = tid & (NH - 1);
        const int c0 = tid >> 7;                    // 0..1, step 2
        const float4 B0 = sH[j];
        const float4 B1 = sH[(j + 16) & (NH - 1)];
        const float4 B2 = sH[(j + 32) & (NH - 1)];
        const float4 B3 = sH[(j + 48) & (NH - 1)];
        #pragma unroll 4
        for (int o = 49 + c0; o <= 64; o += 2) {
            const float4 A = sH[(j + o) & (NH - 1)];
            const int w0 = (o == 64) ? 1 : 2;
            do_pair(A, B0, L0, L1, L2, bN, inv_dx, kc, hbHH, w0);
            do_pair(A, B1, L0, L1, L2, bN, inv_dx, kc, hbHH, 2);
            do_pair(A, B2, L0, L1, L2, bN, inv_dx, kc, hbHH, 2);
            do_pair(A, B3, L0, L1, L2, bN, inv_dx, kc, hbHH, 2);
        }
    }
    // ---- phase 3: HO (all 128x64, w=1). 4-way shared-A: A=sH[i] pairs with
    //      B = sO[j], sO[j+16], sO[j+32], sO[j+48], j in 0..15. ----
    {
        const int j  = tid & 15;
        const int c0 = tid >> 4;                    // 0..15, step 16
        const float4 B0 = sO[j];
        const float4 B1 = sO[j + 16];
        const float4 B2 = sO[j + 32];
        const float4 B3 = sO[j + 48];
        #pragma unroll 4
        for (int i = c0; i < NH; i += 16) {
            const float4 A = sH[i];
            do_pair(A, B0, L0, L1, L2, bN, inv_dx, kc, hbHO, 1);
            do_pair(A, B1, L0, L1, L2, bN, inv_dx, kc, hbHO, 1);
            do_pair(A, B2, L0, L1, L2, bN, inv_dx, kc, hbHO, 1);
            do_pair(A, B3, L0, L1, L2, bN, inv_dx, kc, hbHO, 1);
        }
    }
    __syncthreads();

    // ---- epilogue: u = sum_b h[b]/shell[b] per pair type ----
    const float c43pi = (float)(4.0 / 3.0 * M_PI);
    float a0 = 0.0f, a1 = 0.0f, a2 = 0.0f;
    for (int i = tid; i < nb; i += 256) {
        const float lo = bins[i], hi = bins[i + 1];
        const float inv = __fdividef(1.0f, c43pi * (hi * hi * hi - lo * lo * lo));
        a0 = fmaf((float)hOO[i], inv, a0);
        a1 = fmaf((float)hHH[i], inv, a1);
        a2 = fmaf((float)hHO[i], inv, a2);
    }
    #pragma unroll
    for (int o = 16; o > 0; o >>= 1) {
        a0 += __shfl_xor_sync(0xffffffffu, a0, o);
        a1 += __shfl_xor_sync(0xffffffffu, a1, o);
        a2 += __shfl_xor_sync(0xffffffffu, a2, o);
    }
    if (lane == 0) { usum[wid][0] = a0; usum[wid][1] = a1; usum[wid][2] = a2; }
    __syncthreads();
    if (tid == 0) {
        float s0 = 0.0f, s1 = 0.0f, s2 = 0.0f;
        #pragma unroll
        for (int w = 0; w < 8; w++) {
            s0 += usum[w][0]; s1 += usum[w][1]; s2 += usum[w][2];
        }
        ubc[0] = s0; ubc[1] = s1; ubc[2] = s2;
        atomicAdd(&g_sumU[r * 3 + 0], s0);
        atomicAdd(&g_sumU[r * 3 + 1], s1);
        atomicAdd(&g_sumU[r * 3 + 2], s2);
    }
    __syncthreads();

    // ---- accumulate num[rp,b] += h[b]/u directly ----
    const float iu0 = 1.0f / ubc[0];
    const float iu1 = 1.0f / ubc[1];
    const float iu2 = 1.0f / ubc[2];
    float* n0 = g_num + (size_t)(r * 3 + 0) * NB_MAX;
    float* n1 = g_num + (size_t)(r * 3 + 1) * NB_MAX;
    float* n2 = g_num + (size_t)(r * 3 + 2) * NB_MAX;
    for (int i = tid; i < nb; i += 256) {
        const int h0 = hOO[i], h1 = hHH[i], h2 = hHO[i];
        if (h0) atomicAdd(&n0[i], (float)h0 * iu0);
        if (h1) atomicAdd(&n1[i], (float)h1 * iu1);
        if (h2) atomicAdd(&n2[i], (float)h2 * iu2);
    }
}

// ---------------------------------------------------------------------------
// rdf + MAE from accumulated numerators: blockIdx.x = rp (24 blocks).
// rdf[b] = (sumU * vol/(T*P)/T) * num[b] / shell[b]. Re-zeros its scratch
// for the next graph replay; last block finalizes the per-replica MAE max.
// ---------------------------------------------------------------------------
__global__ __launch_bounds__(256) void rdf_kernel(
    const float* __restrict__ bins,
    const float* __restrict__ lat,
    const float* __restrict__ gt_oo,
    const float* __restrict__ gt_hh,
    const float* __restrict__ gt_ho,
    float* __restrict__ out,
    int T, int nb, int R)
{
    __shared__ float red[256];
    __shared__ int sdone;

    const int rp = blockIdx.x;
    const int p = rp % 3;
    const int r = rp / 3;
    const int tid = threadIdx.x;

    const float vol = lat[0] * lat[1] * lat[2];
    const int P = (p == 0) ? NO * NO : (p == 1) ? NH * NH : NH * NO;
    const float sumU = g_sumU[rp];
    const float SinvT = vol / ((float)T * (float)P) * sumU / (float)T;
    const float* gt = (p == 0) ? gt_oo : (p == 1) ? gt_hh : gt_ho;
    const float* num = g_num + (size_t)rp * NB_MAX;
    const float c43pi = (float)(4.0 / 3.0 * M_PI);

    float* ro = out + ((size_t)r * 3 + p) * nb;
    float myabs = 0.0f;
    for (int b = tid; b < nb; b += 256) {
        const float lo = bins[b], hi = bins[b + 1];
        const float rdf = SinvT * num[b] / (c43pi * (hi * hi * hi - lo * lo * lo));
        ro[b] = rdf;
        myabs += fabsf(rdf - gt[b]);
    }
    red[tid] = myabs;
    __syncthreads();

    // re-zero scratch for the next replay (all reads of num/sumU are done)
    for (int b = tid; b < nb; b += 256) ((float*)num)[b] = 0.0f;
    if (tid == 0) g_sumU[rp] = 0.0f;

    #pragma unroll
    for (int s = 128; s > 0; s >>= 1) {
        if (tid < s) red[tid] += red[tid + s];
        __syncthreads();
    }
    if (tid == 0) {
        g_maes[rp] = 6.0f * red[0] / (float)nb;   // XLIM * mean
        __threadfence();
        unsigned old = atomicAdd(&g_cnt, 1u);
        sdone = (int)(old == (unsigned)(3 * R - 1));
    }
    __syncthreads();
    if (sdone) {
        __threadfence();
        if (tid == 0) g_cnt = 0;                  // reset for next graph replay
        if (tid < R) {
            volatile float* gm = g_maes;
            float m = gm[tid * 3];
            m = fmaxf(m, gm[tid * 3 + 1]);
            m = fmaxf(m, gm[tid * 3 + 2]);
            out[(size_t)R * 3 * nb + tid] = m;
        }
    }
}

// ---------------------------------------------------------------------------
extern "C" void kernel_launch(void* const* d_in, const int* in_sizes, int n_in,
                              void* d_out, int out_size) {
    const float* radii  = (const float*)d_in[0];   // (T,R,N,3)
    const int*   ptypes = (const int*)d_in[1];     // (N,)
    const float* lat    = (const float*)d_in[2];   // (3,)
    const float* bins   = (const float*)d_in[3];   // (nb+1,)
    const float* gt_oo  = (const float*)d_in[4];
    const float* gt_hh  = (const float*)d_in[5];
    const float* gt_ho  = (const float*)d_in[6];
    float* out = (float*)d_out;

    const int nb = in_sizes[3] - 1;                 // 600
    const int N  = in_sizes[1];                     // 192
    const int R  = out_size / (3 * nb + 1);         // 8
    const int T  = in_sizes[0] / (R * N * 3);       // 100

    hist_kernel<<<R * T, 256>>>(radii, ptypes, lat, bins, T, R, N, nb);
    rdf_kernel<<<R * 3, 256>>>(bins, lat, gt_oo, gt_hh, gt_ho, out, T, nb, R);
}